// round 1
// baseline (speedup 1.0000x reference)
#include <cuda_runtime.h>
#include <math.h>

// Problem constants
#define BB 8
#define NN 2048
#define CC 1024
#define KKEEP 1638

// Scratch (allocation-free rule: __device__ globals)
__device__ float g_Q[BB * NN * CC];
__device__ float g_K[BB * NN * CC];
__device__ float g_V[BB * NN * CC];
__device__ float g_S[(size_t)BB * NN * NN];

// ---------------------------------------------------------------------------
// GEMM NT: C[m][n] = scale * sum_k A[m][k] * B[n][k]  (+ bias[n])
// A: [M,K] row-major (lda=K), B: [N,K] row-major (ldb=K), C: [M,N] (ldc=N)
// Batched via blockIdx.z with element strides sA/sB/sC.
// Tiles: 64x64x16, 256 threads, 4x4 per thread.
// ---------------------------------------------------------------------------
__global__ void gemm_nt(const float* __restrict__ A, const float* __restrict__ B,
                        float* __restrict__ C, const float* __restrict__ bias,
                        int M, int N, int K,
                        long long sA, long long sB, long long sC, float scale) {
    __shared__ float As[64][17];
    __shared__ float Bs[64][17];

    A += (size_t)blockIdx.z * sA;
    B += (size_t)blockIdx.z * sB;
    C += (size_t)blockIdx.z * sC;

    const int tid = threadIdx.x;      // 0..255
    const int tx = tid & 15;
    const int ty = tid >> 4;
    const int m0 = blockIdx.y * 64;
    const int n0 = blockIdx.x * 64;

    float acc[4][4] = {};

    for (int k0 = 0; k0 < K; k0 += 16) {
#pragma unroll
        for (int i = 0; i < 4; i++) {
            int lin = tid + i * 256;          // 0..1023
            int r = lin >> 4;                 // 0..63
            int k = lin & 15;                 // 0..15
            As[r][k] = A[(size_t)(m0 + r) * K + k0 + k];
            Bs[r][k] = B[(size_t)(n0 + r) * K + k0 + k];
        }
        __syncthreads();

#pragma unroll
        for (int k = 0; k < 16; k++) {
            float a[4], b[4];
#pragma unroll
            for (int i = 0; i < 4; i++) a[i] = As[ty * 4 + i][k];
#pragma unroll
            for (int j = 0; j < 4; j++) b[j] = Bs[tx * 4 + j][k];
#pragma unroll
            for (int i = 0; i < 4; i++)
#pragma unroll
                for (int j = 0; j < 4; j++) acc[i][j] += a[i] * b[j];
        }
        __syncthreads();
    }

#pragma unroll
    for (int i = 0; i < 4; i++) {
        int m = m0 + ty * 4 + i;
#pragma unroll
        for (int j = 0; j < 4; j++) {
            int n = n0 + tx * 4 + j;
            float v = acc[i][j] * scale;
            if (bias) v += bias[n];
            C[(size_t)m * N + n] = v;
        }
    }
}

// ---------------------------------------------------------------------------
// GEMM NN: C[m][n] = sum_k A[m][k] * B[k][n]
// A: [M,K] row-major (lda=K), B: [K,N] row-major (ldb=N), C: [M,N] (ldc=N)
// ---------------------------------------------------------------------------
__global__ void gemm_nn(const float* __restrict__ A, const float* __restrict__ B,
                        float* __restrict__ C,
                        int M, int N, int K,
                        long long sA, long long sB, long long sC) {
    __shared__ float As[64][17];
    __shared__ float Bs[16][64];

    A += (size_t)blockIdx.z * sA;
    B += (size_t)blockIdx.z * sB;
    C += (size_t)blockIdx.z * sC;

    const int tid = threadIdx.x;
    const int tx = tid & 15;
    const int ty = tid >> 4;
    const int m0 = blockIdx.y * 64;
    const int n0 = blockIdx.x * 64;

    float acc[4][4] = {};

    for (int k0 = 0; k0 < K; k0 += 16) {
#pragma unroll
        for (int i = 0; i < 4; i++) {
            int lin = tid + i * 256;
            int ra = lin >> 4, ka = lin & 15;
            As[ra][ka] = A[(size_t)(m0 + ra) * K + k0 + ka];
            int kb = lin >> 6, nb = lin & 63;
            Bs[kb][nb] = B[(size_t)(k0 + kb) * N + n0 + nb];
        }
        __syncthreads();

#pragma unroll
        for (int k = 0; k < 16; k++) {
            float a[4];
#pragma unroll
            for (int i = 0; i < 4; i++) a[i] = As[ty * 4 + i][k];
            float4 bv = *(const float4*)&Bs[k][tx * 4];
            float b[4] = {bv.x, bv.y, bv.z, bv.w};
#pragma unroll
            for (int i = 0; i < 4; i++)
#pragma unroll
                for (int j = 0; j < 4; j++) acc[i][j] += a[i] * b[j];
        }
        __syncthreads();
    }

#pragma unroll
    for (int i = 0; i < 4; i++) {
        int m = m0 + ty * 4 + i;
#pragma unroll
        for (int j = 0; j < 4; j++) {
            int n = n0 + tx * 4 + j;
            C[(size_t)m * N + n] = acc[i][j];
        }
    }
}

// ---------------------------------------------------------------------------
// Per-row top-k threshold (exact, 4-pass MSB radix select on sortable uint)
// + masked softmax, in place on S. One block (256 threads) per row of 2048.
// Masked entries become exactly 0.0 (matches reference: exp(-1e10-..) -> 0).
// ---------------------------------------------------------------------------
__device__ __forceinline__ unsigned f2u(float f) {
    unsigned b = __float_as_uint(f);
    return (b & 0x80000000u) ? ~b : (b | 0x80000000u);
}
__device__ __forceinline__ float u2f(unsigned u) {
    unsigned b = (u & 0x80000000u) ? (u & 0x7fffffffu) : ~u;
    return __uint_as_float(b);
}

__global__ void topk_softmax(float* __restrict__ S) {
    const size_t row = blockIdx.x;
    float* p = S + row * NN;
    const int tid = threadIdx.x;  // 256 threads, 8 elems each

    __shared__ int hist[256];
    __shared__ int s_digit, s_rem;
    __shared__ unsigned s_warpk[8];
    __shared__ float s_warpf[8];
    __shared__ float s_sum;

    unsigned key[8];
    float val[8];
    unsigned lmax = 0;
#pragma unroll
    for (int i = 0; i < 8; i++) {
        float f = p[tid + i * 256];
        val[i] = f;
        key[i] = f2u(f);
        lmax = max(lmax, key[i]);
    }

    // block max key
    lmax = __reduce_max_sync(0xffffffffu, lmax);
    if ((tid & 31) == 0) s_warpk[tid >> 5] = lmax;
    __syncthreads();
    if (tid == 0) {
        unsigned m = s_warpk[0];
#pragma unroll
        for (int w = 1; w < 8; w++) m = max(m, s_warpk[w]);
        s_warpk[0] = m;
        s_rem = KKEEP;
    }

    // radix select: find key of KKEEP-th largest element
    unsigned prefix = 0, pmask = 0;
    for (int shift = 24; shift >= 0; shift -= 8) {
        hist[tid] = 0;
        __syncthreads();
#pragma unroll
        for (int i = 0; i < 8; i++)
            if ((key[i] & pmask) == prefix)
                atomicAdd(&hist[(key[i] >> shift) & 255], 1);
        __syncthreads();
        if (tid == 0) {
            int remk = s_rem, cum = 0, d = 255;
            for (; d > 0; --d) {
                int c = hist[d];
                if (cum + c >= remk) break;
                cum += c;
            }
            s_digit = d;
            s_rem = remk - cum;
        }
        __syncthreads();
        prefix |= ((unsigned)s_digit) << shift;
        pmask |= 0xFFu << shift;
    }
    const unsigned thr = prefix;
    const float mval = u2f(s_warpk[0]);

    // masked softmax
    float e[8];
    float lsum = 0.f;
#pragma unroll
    for (int i = 0; i < 8; i++) {
        if (key[i] >= thr) {
            e[i] = __expf(val[i] - mval);
            lsum += e[i];
        } else {
            e[i] = 0.f;
        }
    }
#pragma unroll
    for (int o = 16; o > 0; o >>= 1) lsum += __shfl_down_sync(0xffffffffu, lsum, o);
    if ((tid & 31) == 0) s_warpf[tid >> 5] = lsum;
    __syncthreads();
    if (tid == 0) {
        float s = 0.f;
#pragma unroll
        for (int w = 0; w < 8; w++) s += s_warpf[w];
        s_sum = s;
    }
    __syncthreads();
    const float inv = 1.0f / s_sum;
#pragma unroll
    for (int i = 0; i < 8; i++) p[tid + i * 256] = e[i] * inv;
}

// ---------------------------------------------------------------------------
// Launch
// ---------------------------------------------------------------------------
extern "C" void kernel_launch(void* const* d_in, const int* in_sizes, int n_in,
                              void* d_out, int out_size) {
    const float* x  = (const float*)d_in[0];
    const float* Wq = (const float*)d_in[1];
    const float* bq = (const float*)d_in[2];
    const float* Wk = (const float*)d_in[3];
    const float* bk = (const float*)d_in[4];
    const float* Wv = (const float*)d_in[5];
    const float* bv = (const float*)d_in[6];
    float* out = (float*)d_out;

    float *Q, *K, *V, *S;
    cudaGetSymbolAddress((void**)&Q, g_Q);
    cudaGetSymbolAddress((void**)&K, g_K);
    cudaGetSymbolAddress((void**)&V, g_V);
    cudaGetSymbolAddress((void**)&S, g_S);

    dim3 thr(256);

    // QKV projections: [16384,1024] x [1024,1024]^T + bias
    dim3 gqkv(CC / 64, (BB * NN) / 64, 1);
    gemm_nt<<<gqkv, thr>>>(x, Wq, Q, bq, BB * NN, CC, CC, 0, 0, 0, 1.0f);
    gemm_nt<<<gqkv, thr>>>(x, Wk, K, bk, BB * NN, CC, CC, 0, 0, 0, 1.0f);
    gemm_nt<<<gqkv, thr>>>(x, Wv, V, bv, BB * NN, CC, CC, 0, 0, 0, 1.0f);

    // S = Q K^T / sqrt(C), batched over B
    dim3 gs(NN / 64, NN / 64, BB);
    gemm_nt<<<gs, thr>>>(Q, K, S, nullptr, NN, NN, CC,
                         (long long)NN * CC, (long long)NN * CC,
                         (long long)NN * NN, 0.03125f);

    // exact top-k mask + softmax (in place)
    topk_softmax<<<BB * NN, 256>>>(S);

    // O = P V, batched over B
    dim3 go(CC / 64, NN / 64, BB);
    gemm_nn<<<go, thr>>>(S, V, out, NN, CC, NN,
                         (long long)NN * NN, (long long)NN * CC,
                         (long long)NN * CC);
}

// round 3
// speedup vs baseline: 2.2704x; 2.2704x over previous
#include <cuda_runtime.h>
#include <math.h>

// Problem constants
#define BB 8
#define NN 2048
#define CC 1024
#define KKEEP 1638

// Scratch (allocation-free rule: __device__ globals)
__device__ float g_Q[BB * NN * CC];
__device__ float g_K[BB * NN * CC];
__device__ float g_V[BB * NN * CC];
__device__ float g_S[(size_t)BB * NN * NN];

// ---------------------------------------------------------------------------
// TF32 helpers
// ---------------------------------------------------------------------------
__device__ __forceinline__ unsigned f2tf32(float x) {
    unsigned r;
    asm("cvt.rna.tf32.f32 %0, %1;" : "=r"(r) : "f"(x));
    return r;
}

__device__ __forceinline__ void mma8(float* c, const unsigned* a, const unsigned* b) {
    asm volatile(
        "mma.sync.aligned.m16n8k8.row.col.f32.tf32.tf32.f32 "
        "{%0,%1,%2,%3}, {%4,%5,%6,%7}, {%8,%9}, {%0,%1,%2,%3};"
        : "+f"(c[0]), "+f"(c[1]), "+f"(c[2]), "+f"(c[3])
        : "r"(a[0]), "r"(a[1]), "r"(a[2]), "r"(a[3]), "r"(b[0]), "r"(b[1]));
}

// ---------------------------------------------------------------------------
// Tensor-core GEMM, 128x128x16 tile, 256 threads, 8 warps (2x4) of 64x32.
//   THREEX: 1 -> 3xTF32 (fp32-accurate), 0 -> 1xTF32
//   TRANSB: true  -> B is [N,K] row-major (NT GEMM, C = A * B^T)
//           false -> B is [K,N] row-major (NN GEMM, C = A * B)
//   BIAS:   add bias[n]
// C[m][n] = scale * sum_k A[m][k]*Bop[k][n] (+ bias[n])
// Batched over blockIdx.z with element strides sA/sB/sC.
// ---------------------------------------------------------------------------
template <int THREEX, bool TRANSB, bool BIAS>
__global__ void __launch_bounds__(256, 1)
mma_gemm(const float* __restrict__ A, const float* __restrict__ B,
         float* __restrict__ C, const float* __restrict__ bias,
         int M, int N, int K,
         long long sA, long long sB, long long sC, float scale) {
    __shared__ float As[2][16][136];
    __shared__ float Bs[2][16][136];

    A += (size_t)blockIdx.z * sA;
    B += (size_t)blockIdx.z * sB;
    C += (size_t)blockIdx.z * sC;

    const int t = threadIdx.x;
    const int lane = t & 31;
    const int warp = t >> 5;
    const int wm = warp & 1;   // 2 warps along M
    const int wn = warp >> 1;  // 4 warps along N
    const int g = lane >> 2;   // 0..7
    const int tg = lane & 3;   // 0..3

    const int m0 = blockIdx.y * 128;
    const int n0 = blockIdx.x * 128;
    const int aBase = wm * 64;
    const int bBase = wn * 32;

    float acc[4][4][4];
#pragma unroll
    for (int i = 0; i < 4; i++)
#pragma unroll
        for (int j = 0; j < 4; j++)
#pragma unroll
            for (int r = 0; r < 4; r++) acc[i][j][r] = 0.f;

    const int NK = K / 16;
    float4 ra[2], rb[2];

    // --- global load of tile kt into registers ---
    auto load_tile = [&](int kt) {
        const int k0 = kt * 16;
#pragma unroll
        for (int i = 0; i < 2; i++) {
            int idx = t + i * 256;
            int row = idx >> 2, kq = idx & 3;
            ra[i] = *(const float4*)&A[(size_t)(m0 + row) * K + k0 + kq * 4];
        }
        if (TRANSB) {
#pragma unroll
            for (int i = 0; i < 2; i++) {
                int idx = t + i * 256;
                int row = idx >> 2, kq = idx & 3;
                rb[i] = *(const float4*)&B[(size_t)(n0 + row) * K + k0 + kq * 4];
            }
        } else {
#pragma unroll
            for (int i = 0; i < 2; i++) {
                int idx = t + i * 256;
                int kk = idx >> 5, n4 = (idx & 31) * 4;
                rb[i] = *(const float4*)&B[(size_t)(k0 + kk) * N + n0 + n4];
            }
        }
    };

    // --- store registers into smem buffer ---
    auto store_tile = [&](int buf) {
#pragma unroll
        for (int i = 0; i < 2; i++) {
            int idx = t + i * 256;
            int row = idx >> 2, kq = idx & 3;
            As[buf][kq * 4 + 0][row] = ra[i].x;
            As[buf][kq * 4 + 1][row] = ra[i].y;
            As[buf][kq * 4 + 2][row] = ra[i].z;
            As[buf][kq * 4 + 3][row] = ra[i].w;
        }
        if (TRANSB) {
#pragma unroll
            for (int i = 0; i < 2; i++) {
                int idx = t + i * 256;
                int row = idx >> 2, kq = idx & 3;
                Bs[buf][kq * 4 + 0][row] = rb[i].x;
                Bs[buf][kq * 4 + 1][row] = rb[i].y;
                Bs[buf][kq * 4 + 2][row] = rb[i].z;
                Bs[buf][kq * 4 + 3][row] = rb[i].w;
            }
        } else {
#pragma unroll
            for (int i = 0; i < 2; i++) {
                int idx = t + i * 256;
                int kk = idx >> 5, n4 = (idx & 31) * 4;
                *(float4*)&Bs[buf][kk][n4] = rb[i];
            }
        }
    };

    load_tile(0);
    store_tile(0);
    __syncthreads();

    for (int kt = 0; kt < NK; kt++) {
        const int buf = kt & 1;
        if (kt + 1 < NK) load_tile(kt + 1);

        // --- compute on buf ---
#pragma unroll
        for (int ks = 0; ks < 16; ks += 8) {
            float af[4][4], bf[4][2];
#pragma unroll
            for (int mt = 0; mt < 4; mt++) {
                int mo = aBase + mt * 16 + g;
                af[mt][0] = As[buf][ks + tg][mo];
                af[mt][1] = As[buf][ks + tg][mo + 8];
                af[mt][2] = As[buf][ks + tg + 4][mo];
                af[mt][3] = As[buf][ks + tg + 4][mo + 8];
            }
#pragma unroll
            for (int nt = 0; nt < 4; nt++) {
                int no = bBase + nt * 8 + g;
                bf[nt][0] = Bs[buf][ks + tg][no];
                bf[nt][1] = Bs[buf][ks + tg + 4][no];
            }

            unsigned ah[4][4], bh[4][2];
#pragma unroll
            for (int mt = 0; mt < 4; mt++)
#pragma unroll
                for (int r = 0; r < 4; r++) ah[mt][r] = f2tf32(af[mt][r]);
#pragma unroll
            for (int nt = 0; nt < 4; nt++)
#pragma unroll
                for (int r = 0; r < 2; r++) bh[nt][r] = f2tf32(bf[nt][r]);

            if (THREEX) {
                unsigned al[4][4], bl[4][2];
#pragma unroll
                for (int mt = 0; mt < 4; mt++)
#pragma unroll
                    for (int r = 0; r < 4; r++)
                        al[mt][r] = f2tf32(af[mt][r] - __uint_as_float(ah[mt][r]));
#pragma unroll
                for (int nt = 0; nt < 4; nt++)
#pragma unroll
                    for (int r = 0; r < 2; r++)
                        bl[nt][r] = f2tf32(bf[nt][r] - __uint_as_float(bh[nt][r]));
#pragma unroll
                for (int mt = 0; mt < 4; mt++)
#pragma unroll
                    for (int nt = 0; nt < 4; nt++) {
                        mma8(acc[mt][nt], al[mt], bh[nt]);
                        mma8(acc[mt][nt], ah[mt], bl[nt]);
                        mma8(acc[mt][nt], ah[mt], bh[nt]);
                    }
            } else {
#pragma unroll
                for (int mt = 0; mt < 4; mt++)
#pragma unroll
                    for (int nt = 0; nt < 4; nt++) mma8(acc[mt][nt], ah[mt], bh[nt]);
            }
        }

        __syncthreads();
        if (kt + 1 < NK) {
            store_tile((kt + 1) & 1);
            __syncthreads();
        }
    }

    // --- epilogue ---
#pragma unroll
    for (int mt = 0; mt < 4; mt++) {
        int m = m0 + aBase + mt * 16 + g;
#pragma unroll
        for (int nt = 0; nt < 4; nt++) {
            int n = n0 + bBase + nt * 8 + tg * 2;
            float b0 = 0.f, b1 = 0.f;
            if (BIAS) { b0 = bias[n]; b1 = bias[n + 1]; }
            float2 v0 = make_float2(acc[mt][nt][0] * scale + b0,
                                    acc[mt][nt][1] * scale + b1);
            float2 v1 = make_float2(acc[mt][nt][2] * scale + b0,
                                    acc[mt][nt][3] * scale + b1);
            *(float2*)&C[(size_t)m * N + n] = v0;
            *(float2*)&C[(size_t)(m + 8) * N + n] = v1;
        }
    }
}

// ---------------------------------------------------------------------------
// Per-row exact top-k threshold (4-pass MSB radix select) + masked softmax.
// One block (256 threads) per row of 2048. Masked entries -> exactly 0.
// ---------------------------------------------------------------------------
__device__ __forceinline__ unsigned f2u(float f) {
    unsigned b = __float_as_uint(f);
    return (b & 0x80000000u) ? ~b : (b | 0x80000000u);
}
__device__ __forceinline__ float u2f(unsigned u) {
    unsigned b = (u & 0x80000000u) ? (u & 0x7fffffffu) : ~u;
    return __uint_as_float(b);
}

__global__ void topk_softmax(float* __restrict__ S) {
    const size_t row = blockIdx.x;
    float* p = S + row * NN;
    const int tid = threadIdx.x;  // 256 threads, 8 elems each

    __shared__ int hist[256];
    __shared__ int s_digit, s_rem;
    __shared__ unsigned s_warpk[8];
    __shared__ float s_warpf[8];
    __shared__ float s_sum;

    unsigned key[8];
    float val[8];
    unsigned lmax = 0;
#pragma unroll
    for (int i = 0; i < 8; i++) {
        float f = p[tid + i * 256];
        val[i] = f;
        key[i] = f2u(f);
        lmax = max(lmax, key[i]);
    }

    lmax = __reduce_max_sync(0xffffffffu, lmax);
    if ((tid & 31) == 0) s_warpk[tid >> 5] = lmax;
    __syncthreads();
    if (tid == 0) {
        unsigned m = s_warpk[0];
#pragma unroll
        for (int w = 1; w < 8; w++) m = max(m, s_warpk[w]);
        s_warpk[0] = m;
        s_rem = KKEEP;
    }

    unsigned prefix = 0, pmask = 0;
    for (int shift = 24; shift >= 0; shift -= 8) {
        hist[tid] = 0;
        __syncthreads();
#pragma unroll
        for (int i = 0; i < 8; i++)
            if ((key[i] & pmask) == prefix)
                atomicAdd(&hist[(key[i] >> shift) & 255], 1);
        __syncthreads();
        if (tid == 0) {
            int remk = s_rem, cum = 0, d = 255;
            for (; d > 0; --d) {
                int c = hist[d];
                if (cum + c >= remk) break;
                cum += c;
            }
            s_digit = d;
            s_rem = remk - cum;
        }
        __syncthreads();
        prefix |= ((unsigned)s_digit) << shift;
        pmask |= 0xFFu << shift;
    }
    const unsigned thr = prefix;
    const float mval = u2f(s_warpk[0]);

    float e[8];
    float lsum = 0.f;
#pragma unroll
    for (int i = 0; i < 8; i++) {
        if (key[i] >= thr) {
            e[i] = __expf(val[i] - mval);
            lsum += e[i];
        } else {
            e[i] = 0.f;
        }
    }
#pragma unroll
    for (int o = 16; o > 0; o >>= 1) lsum += __shfl_down_sync(0xffffffffu, lsum, o);
    if ((tid & 31) == 0) s_warpf[tid >> 5] = lsum;
    __syncthreads();
    if (tid == 0) {
        float s = 0.f;
#pragma unroll
        for (int w = 0; w < 8; w++) s += s_warpf[w];
        s_sum = s;
    }
    __syncthreads();
    const float inv = 1.0f / s_sum;
#pragma unroll
    for (int i = 0; i < 8; i++) p[tid + i * 256] = e[i] * inv;
}

// ---------------------------------------------------------------------------
// Launch
// ---------------------------------------------------------------------------
extern "C" void kernel_launch(void* const* d_in, const int* in_sizes, int n_in,
                              void* d_out, int out_size) {
    const float* x  = (const float*)d_in[0];
    const float* Wq = (const float*)d_in[1];
    const float* bq = (const float*)d_in[2];
    const float* Wk = (const float*)d_in[3];
    const float* bk = (const float*)d_in[4];
    const float* Wv = (const float*)d_in[5];
    const float* bv = (const float*)d_in[6];
    float* out = (float*)d_out;

    float *Q, *K, *V, *S;
    cudaGetSymbolAddress((void**)&Q, g_Q);
    cudaGetSymbolAddress((void**)&K, g_K);
    cudaGetSymbolAddress((void**)&V, g_V);
    cudaGetSymbolAddress((void**)&S, g_S);

    dim3 thr(256);

    // QKV projections: [16384,1024] x [1024,1024]^T + bias
    dim3 gqkv(CC / 128, (BB * NN) / 128, 1);
    // Q, K feed the top-k logits -> need fp32-grade accuracy (3xTF32)
    mma_gemm<1, true, true><<<gqkv, thr>>>(x, Wq, Q, bq, BB * NN, CC, CC, 0, 0, 0, 1.0f);
    mma_gemm<1, true, true><<<gqkv, thr>>>(x, Wk, K, bk, BB * NN, CC, CC, 0, 0, 0, 1.0f);
    // V only perturbs the output linearly -> 1xTF32 is fine
    mma_gemm<0, true, true><<<gqkv, thr>>>(x, Wv, V, bv, BB * NN, CC, CC, 0, 0, 0, 1.0f);

    // S = Q K^T / sqrt(C): accuracy-critical (top-k boundary) -> 3xTF32
    dim3 gs(NN / 128, NN / 128, BB);
    mma_gemm<1, true, false><<<gs, thr>>>(Q, K, S, nullptr, NN, NN, CC,
                                          (long long)NN * CC, (long long)NN * CC,
                                          (long long)NN * NN, 0.03125f);

    // exact top-k mask + softmax (in place)
    topk_softmax<<<BB * NN, 256>>>(S);

    // O = P V (1xTF32)
    dim3 go(CC / 128, NN / 128, BB);
    mma_gemm<0, false, false><<<go, thr>>>(S, V, out, nullptr, NN, CC, NN,
                                           (long long)NN * NN, (long long)NN * CC,
                                           (long long)NN * CC, 1.0f);
}